// round 7
// baseline (speedup 1.0000x reference)
#include <cuda_runtime.h>
#include <cstdint>

#define NPART   100000
#define NFRAMES 500

// Scratch (no allocation allowed): per-frame keys + integer flip thresholds.
__device__ uint2    g_keys[NFRAMES];
__device__ uint32_t g_thresh[2];

__device__ __forceinline__ uint32_t rotl32(uint32_t x, int r) {
    return __funnelshift_l(x, x, r);  // single SHF
}

// Exact threefry2x32 (20 rounds, 5 key injections).
__device__ __forceinline__ void threefry_plain(uint32_t k0, uint32_t k1,
                                               uint32_t x0, uint32_t x1,
                                               uint32_t &o0, uint32_t &o1) {
    uint32_t ks2 = k0 ^ k1 ^ 0x1BD11BDAu;
    x0 += k0; x1 += k1;
#define RND(r) { x0 += x1; x1 = rotl32(x1, r); x1 ^= x0; }
    RND(13) RND(15) RND(26) RND(6)
    x0 += k1;  x1 += ks2 + 1u;
    RND(17) RND(29) RND(16) RND(24)
    x0 += ks2; x1 += k0 + 2u;
    RND(13) RND(15) RND(26) RND(6)
    x0 += k0;  x1 += k1 + 3u;
    RND(17) RND(29) RND(16) RND(24)
    x0 += k1;  x1 += ks2 + 4u;
    RND(13) RND(15) RND(26) RND(6)
    x0 += ks2; x1 += k0 + 5u;
#undef RND
    o0 = x0; o1 = x1;
}

// ceil-threshold: count of integers m with m * 2^-23 < X (exact pow2 scale).
__device__ __forceinline__ uint32_t thresh_from_prob(float p) {
    float X = p * 8388608.0f;
    uint32_t T = (uint32_t)X;
    if ((float)T < X) T++;
    return T;
}

// jax_threefry_partitionable derivations (verified rel_err = 0).
__global__ void setup_kernel(const int* __restrict__ seed_ptr) {
    int tid = blockIdx.x * blockDim.x + threadIdx.x;
    long long seed = (long long)(*seed_ptr);
    uint32_t k0 = (uint32_t)(((unsigned long long)seed) >> 32);
    uint32_t k1 = (uint32_t)seed;

    uint32_t kp0, kp1, ks0, ks1;
    threefry_plain(k0, k1, 0u, 0u, kp0, kp1);
    threefry_plain(k0, k1, 0u, 1u, ks0, ks1);

    if (tid < NFRAMES) {
        uint32_t o0, o1;
        threefry_plain(ks0, ks1, 0u, (uint32_t)tid, o0, o1);
        g_keys[tid] = make_uint2(o0, o1);
    }
    if (tid == 0) {
        uint32_t o0, o1;
        threefry_plain(kp0, kp1, 0u, 0u, o0, o1);
        uint32_t bits = o0 ^ o1;
        float u = __uint_as_float((bits >> 9) | 0x3f800000u) - 1.0f;
        float p = u * 0.001f;
        g_thresh[0] = thresh_from_prob(0.2f);
        g_thresh[1] = thresh_from_prob(p);
    }
}

// Hot path: 4 independent particles per thread (ILP=4), plain short-chain
// rounds (no forced pipe migration — it lengthened the critical path, R4/R6).
__global__ void __launch_bounds__(64)
hmm_kernel(const float* __restrict__ initial, float4* __restrict__ out) {
    int t = blockIdx.x * blockDim.x + threadIdx.x;
    if (t >= NPART / 4) return;

    const uint32_t t0 = g_thresh[0];
    const uint32_t t1 = g_thresh[1];

    const int nbase = 4 * t;                  // particles nbase .. nbase+3
    // one-hot -> state bits (initial[2n+1] is the "state 1" column)
    const float4 i01 = *(const float4*)(initial + 2 * nbase);
    const float4 i23 = *(const float4*)(initial + 2 * nbase + 4);
    uint32_t s0 = (i01.y > 0.5f) ? 1u : 0u;
    uint32_t s1 = (i01.w > 0.5f) ? 1u : 0u;
    uint32_t s2 = (i23.y > 0.5f) ? 1u : 0u;
    uint32_t s3 = (i23.w > 0.5f) ? 1u : 0u;

    const uint32_t jb = 8u * (uint32_t)t;     // 2 * nbase

    float4* optr = out + 2 * t;               // two float4 slots per thread/frame

#pragma unroll 2
    for (int f = 0; f < NFRAMES; f++) {
        const uint2 key = __ldg(&g_keys[f]);
        const uint32_t k0 = key.x, k1 = key.y;
        const uint32_t ks2 = k0 ^ k1 ^ 0x1BD11BDAu;

        // counters: (hi=0, lo=2n+s); x0 init = 0 + k0, x1 init = lo + k1
        uint32_t a0 = k0, a1 = (jb + 0u + s0) + k1;
        uint32_t b0 = k0, b1 = (jb + 2u + s1) + k1;
        uint32_t c0 = k0, c1 = (jb + 4u + s2) + k1;
        uint32_t d0 = k0, d1 = (jb + 6u + s3) + k1;

#define RND4(r) { a0 += a1; a1 = rotl32(a1, r) ^ a0; \
                  b0 += b1; b1 = rotl32(b1, r) ^ b0; \
                  c0 += c1; c1 = rotl32(c1, r) ^ c0; \
                  d0 += d1; d1 = rotl32(d1, r) ^ d0; }
#define INJ4(p0, p1, c) { a0 += (p0); a1 += (p1) + (c); \
                          b0 += (p0); b1 += (p1) + (c); \
                          c0 += (p0); c1 += (p1) + (c); \
                          d0 += (p0); d1 += (p1) + (c); }
        RND4(13) RND4(15) RND4(26) RND4(6)
        INJ4(k1, ks2, 1u)
        RND4(17) RND4(29) RND4(16) RND4(24)
        INJ4(ks2, k0, 2u)
        RND4(13) RND4(15) RND4(26) RND4(6)
        INJ4(k0, k1, 3u)
        RND4(17) RND4(29) RND4(16) RND4(24)
        INJ4(k1, ks2, 4u)
        RND4(13) RND4(15) RND4(26) RND4(6)
        INJ4(ks2, k0, 5u)
#undef RND4
#undef INJ4

        uint32_t m0 = (a0 ^ a1) >> 9;         // folded draw -> 23-bit mantissa
        uint32_t m1 = (b0 ^ b1) >> 9;
        uint32_t m2 = (c0 ^ c1) >> 9;
        uint32_t m3 = (d0 ^ d1) >> 9;
        s0 ^= (m0 < (s0 ? t1 : t0)) ? 1u : 0u;
        s1 ^= (m1 < (s1 ? t1 : t0)) ? 1u : 0u;
        s2 ^= (m2 < (s2 ? t1 : t0)) ? 1u : 0u;
        s3 ^= (m3 < (s3 ? t1 : t0)) ? 1u : 0u;

        optr[0] = make_float4(s0 ? 0.0f : 1.0f, s0 ? 1.0f : 0.0f,
                              s1 ? 0.0f : 1.0f, s1 ? 1.0f : 0.0f);
        optr[1] = make_float4(s2 ? 0.0f : 1.0f, s2 ? 1.0f : 0.0f,
                              s3 ? 0.0f : 1.0f, s3 ? 1.0f : 0.0f);
        optr += NPART / 2;                    // next frame (NPART*2 floats)
    }
}

extern "C" void kernel_launch(void* const* d_in, const int* in_sizes, int n_in,
                              void* d_out, int out_size) {
    const float* initial = (const float*)d_in[0];
    const int*   seed    = (const int*)d_in[1];
    float4*      out     = (float4*)d_out;
    (void)in_sizes; (void)n_in; (void)out_size;

    setup_kernel<<<2, 256>>>(seed);
    int threads_needed = NPART / 4;                 // 25000
    int blocks = (threads_needed + 63) / 64;        // 391 blocks of 64
    hmm_kernel<<<blocks, 64>>>(initial, out);
}

// round 8
// speedup vs baseline: 1.4150x; 1.4150x over previous
#include <cuda_runtime.h>
#include <cstdint>

#define NPART   100000
#define NFRAMES 500

// Scratch (no allocation allowed): per-frame keys + integer flip thresholds.
__device__ uint2    g_keys[NFRAMES];
__device__ uint32_t g_thresh[2];

__device__ __forceinline__ uint32_t rotl32(uint32_t x, int r) {
    return __funnelshift_l(x, x, r);  // single SHF
}

// Exact threefry2x32 (20 rounds, 5 key injections).
__device__ __forceinline__ void threefry_plain(uint32_t k0, uint32_t k1,
                                               uint32_t x0, uint32_t x1,
                                               uint32_t &o0, uint32_t &o1) {
    uint32_t ks2 = k0 ^ k1 ^ 0x1BD11BDAu;
    x0 += k0; x1 += k1;
#define RND(r) { x0 += x1; x1 = rotl32(x1, r); x1 ^= x0; }
    RND(13) RND(15) RND(26) RND(6)
    x0 += k1;  x1 += ks2 + 1u;
    RND(17) RND(29) RND(16) RND(24)
    x0 += ks2; x1 += k0 + 2u;
    RND(13) RND(15) RND(26) RND(6)
    x0 += k0;  x1 += k1 + 3u;
    RND(17) RND(29) RND(16) RND(24)
    x0 += k1;  x1 += ks2 + 4u;
    RND(13) RND(15) RND(26) RND(6)
    x0 += ks2; x1 += k0 + 5u;
#undef RND
    o0 = x0; o1 = x1;
}

// ceil-threshold: count of integers m with m * 2^-23 < X (exact pow2 scale).
__device__ __forceinline__ uint32_t thresh_from_prob(float p) {
    float X = p * 8388608.0f;
    uint32_t T = (uint32_t)X;
    if ((float)T < X) T++;
    return T;
}

// jax_threefry_partitionable derivations (verified rel_err = 0).
__global__ void setup_kernel(const int* __restrict__ seed_ptr) {
    int tid = blockIdx.x * blockDim.x + threadIdx.x;
    long long seed = (long long)(*seed_ptr);
    uint32_t k0 = (uint32_t)(((unsigned long long)seed) >> 32);
    uint32_t k1 = (uint32_t)seed;

    uint32_t kp0, kp1, ks0, ks1;
    threefry_plain(k0, k1, 0u, 0u, kp0, kp1);
    threefry_plain(k0, k1, 0u, 1u, ks0, ks1);

    if (tid < NFRAMES) {
        uint32_t o0, o1;
        threefry_plain(ks0, ks1, 0u, (uint32_t)tid, o0, o1);
        g_keys[tid] = make_uint2(o0, o1);
    }
    if (tid == 0) {
        uint32_t o0, o1;
        threefry_plain(kp0, kp1, 0u, 0u, o0, o1);
        uint32_t bits = o0 ^ o1;
        float u = __uint_as_float((bits >> 9) | 0x3f800000u) - 1.0f;
        float p = u * 0.001f;
        g_thresh[0] = thresh_from_prob(0.2f);
        g_thresh[1] = thresh_from_prob(p);
    }
}

// Hot path: 2 particles/thread (best TLP/ILP balance, R5), block=32 for
// wave-quantization 0.96, software-pipelined key prefetch.
__global__ void __launch_bounds__(32)
hmm_kernel(const float* __restrict__ initial, float4* __restrict__ out) {
    int t = blockIdx.x * blockDim.x + threadIdx.x;
    if (t >= NPART / 2) return;

    const uint32_t t0 = g_thresh[0];
    const uint32_t t1 = g_thresh[1];

    const int na = 2 * t;
    uint32_t sa = (initial[2 * na + 1] > 0.5f) ? 1u : 0u;
    uint32_t sb = (initial[2 * na + 3] > 0.5f) ? 1u : 0u;

    const uint32_t ja_base = 4u * (uint32_t)t;
    const uint32_t jb_base = 4u * (uint32_t)t + 2u;

    float4* optr = out + t;

    // pipeline: key for frame f already in registers at loop top
    uint2 key = __ldg(&g_keys[0]);

#pragma unroll 2
    for (int f = 0; f < NFRAMES; f++) {
        const uint32_t k0 = key.x, k1 = key.y;
        const uint32_t ks2 = k0 ^ k1 ^ 0x1BD11BDAu;

        // prefetch next frame's key; scoreboard drains behind ~70 instrs below
        if (f + 1 < NFRAMES) key = __ldg(&g_keys[f + 1]);

        uint32_t a0 = k0, a1 = (ja_base + sa) + k1;
        uint32_t b0 = k0, b1 = (jb_base + sb) + k1;

#define RND2(r) { a0 += a1; a1 = rotl32(a1, r) ^ a0; \
                  b0 += b1; b1 = rotl32(b1, r) ^ b0; }
#define INJ2(p0, p1, c) { a0 += (p0); a1 += (p1) + (c); \
                          b0 += (p0); b1 += (p1) + (c); }
        RND2(13) RND2(15) RND2(26) RND2(6)
        INJ2(k1, ks2, 1u)
        RND2(17) RND2(29) RND2(16) RND2(24)
        INJ2(ks2, k0, 2u)
        RND2(13) RND2(15) RND2(26) RND2(6)
        INJ2(k0, k1, 3u)
        RND2(17) RND2(29) RND2(16) RND2(24)
        INJ2(k1, ks2, 4u)
        RND2(13) RND2(15) RND2(26) RND2(6)
        INJ2(ks2, k0, 5u)
#undef RND2
#undef INJ2

        uint32_t ma = (a0 ^ a1) >> 9;          // folded draw -> 23-bit mantissa
        uint32_t mb = (b0 ^ b1) >> 9;
        sa ^= (ma < (sa ? t1 : t0)) ? 1u : 0u;
        sb ^= (mb < (sb ? t1 : t0)) ? 1u : 0u;

        *optr = make_float4(sa ? 0.0f : 1.0f, sa ? 1.0f : 0.0f,
                            sb ? 0.0f : 1.0f, sb ? 1.0f : 0.0f);
        optr += NPART / 2;
    }
}

extern "C" void kernel_launch(void* const* d_in, const int* in_sizes, int n_in,
                              void* d_out, int out_size) {
    const float* initial = (const float*)d_in[0];
    const int*   seed    = (const int*)d_in[1];
    float4*      out     = (float4*)d_out;
    (void)in_sizes; (void)n_in; (void)out_size;

    setup_kernel<<<2, 256>>>(seed);
    int threads_needed = NPART / 2;                 // 50000
    int blocks = (threads_needed + 31) / 32;        // 1563 blocks of 32
    hmm_kernel<<<blocks, 32>>>(initial, out);
}